// round 2
// baseline (speedup 1.0000x reference)
#include <cuda_runtime.h>
#include <cstdint>

#define NN 1024
#define DD 256
#define HH 32
#define OUTS 64
#define NBINS 65

// scratch for projections (device globals: no allocation allowed)
__device__ float g_left[NN * HH];
__device__ float g_right[NN * HH];

// ---------------------------------------------------------------------------
// packed f32x2 helpers (sm_100+ PTX; ptxas never auto-fuses these)
// ---------------------------------------------------------------------------
__device__ __forceinline__ unsigned long long pk2(float a, float b) {
    unsigned long long r;
    asm("mov.b64 %0, {%1, %2};" : "=l"(r) : "f"(a), "f"(b));
    return r;
}
__device__ __forceinline__ void fma2(unsigned long long& d,
                                     unsigned long long a,
                                     unsigned long long b) {
    asm("fma.rn.f32x2 %0, %1, %2, %0;" : "+l"(d) : "l"(a), "l"(b));
}
__device__ __forceinline__ float2 up2(unsigned long long a) {
    float2 f;
    asm("mov.b64 {%0, %1}, %2;" : "=f"(f.x), "=f"(f.y) : "l"(a));
    return f;
}

// JAX approximate (tanh) GELU; tanh(u) = 1 - 2/(1+exp(2u))
__device__ __forceinline__ float gelu_tanh(float x) {
    float u  = 0.7978845608028654f * (x + 0.044715f * x * x * x);
    float e  = __expf(2.0f * u);            // inf for large u -> t=1; 0 for very negative -> t=-1
    float t  = 1.0f - __fdividef(2.0f, 1.0f + e);
    return 0.5f * x * (1.0f + t);
}

// ---------------------------------------------------------------------------
// Projection: left = local @ W_left, right = local @ W_right   [1024,256]@[256,32]
// ---------------------------------------------------------------------------
__global__ void proj_kernel(const float* __restrict__ local,
                            const float* __restrict__ Wl,
                            const float* __restrict__ Wr) {
    int idx  = blockIdx.x * blockDim.x + threadIdx.x;   // 65536 threads
    int h    = idx & 31;
    int n    = (idx >> 5) & (NN - 1);
    int side = idx >> 15;
    const float* W = side ? Wr : Wl;
    float*       g = side ? g_right : g_left;

    const float4* row4 = reinterpret_cast<const float4*>(local + (size_t)n * DD);
    float acc = 0.f;
#pragma unroll
    for (int d4 = 0; d4 < DD / 4; ++d4) {
        float4 r = row4[d4];
        int d = d4 * 4;
        acc += r.x * W[(d + 0) * HH + h];
        acc += r.y * W[(d + 1) * HH + h];
        acc += r.z * W[(d + 2) * HH + h];
        acc += r.w * W[(d + 3) * HH + h];
    }
    g[n * HH + h] = acc;
}

// ---------------------------------------------------------------------------
// Main fused pair kernel: 16x16 pairs per block, one pair per thread
// ---------------------------------------------------------------------------
__global__ __launch_bounds__(256, 2)
void pair_kernel(const int* __restrict__ resi,
                 const int* __restrict__ chain,
                 const int* __restrict__ batch,
                 const int* __restrict__ mask,     // 4-byte elements; nonzero bits == true
                 const float* __restrict__ W_relpos,
                 const float* __restrict__ ln_scale,
                 const float* __restrict__ ln_offset,
                 const float* __restrict__ W_hidden,
                 const float* __restrict__ W_out,
                 float* __restrict__ out) {
    __shared__ float sWh[HH * HH];          // 4 KB, broadcast reads
    __shared__ float sWo[HH * OUTS];        // 8 KB, broadcast reads
    __shared__ float sRel[NBINS * 33];      // pad 33: conflict-free scalar reads
    __shared__ float sL[16 * 33];
    __shared__ float sR[16 * 33];
    __shared__ float sScale[HH], sOff[HH];

    const int tid = threadIdx.x;
    const int i0 = blockIdx.y * 16, j0 = blockIdx.x * 16;

    for (int k = tid; k < HH * HH; k += 256) sWh[k] = W_hidden[k];
    for (int k = tid; k < HH * OUTS; k += 256) sWo[k] = W_out[k];
    for (int k = tid; k < NBINS * HH; k += 256)
        sRel[(k >> 5) * 33 + (k & 31)] = W_relpos[k];
    for (int k = tid; k < 16 * HH; k += 256) {
        int r = k >> 5, h = k & 31;
        sL[r * 33 + h] = g_left[(i0 + r) * HH + h];
        sR[r * 33 + h] = g_right[(j0 + r) * HH + h];
    }
    if (tid < HH) { sScale[tid] = ln_scale[tid]; sOff[tid] = ln_offset[tid]; }
    __syncthreads();

    const int tx = tid & 15, ty = tid >> 4;
    const int i = i0 + ty, j = j0 + tx;

    float4* out4 = reinterpret_cast<float4*>(out) + ((size_t)(i * NN + j) << 4);

    const int  bi = batch[i], bj = batch[j];
    const bool same_batch = (bi == bj);
    const bool pm = same_batch && (mask[i] != 0) && (mask[j] != 0);
    if (!pm) {
        float4 z = make_float4(0.f, 0.f, 0.f, 0.f);
#pragma unroll
        for (int q = 0; q < 16; ++q) __stcs(&out4[q], z);
        return;
    }

    const bool same_chain = same_batch && (chain[i] == chain[j]);
    int diff = resi[i] - resi[j];
    diff = min(max(diff, -32), 32) + 32;

    // ---- pair build + layernorm (fp32, in registers) ----
    const float* relrow = &sRel[diff * 33];
    const float* lrow   = &sL[ty * 33];
    const float* rrow   = &sR[tx * 33];

    float p[HH];
    float mu = 0.f;
#pragma unroll
    for (int h = 0; h < HH; ++h) {
        float v = lrow[h] + rrow[h];
        if (same_chain) v += relrow[h];
        p[h] = v;
        mu += v;
    }
    mu *= (1.f / HH);
    float var = 0.f;
#pragma unroll
    for (int h = 0; h < HH; ++h) { float d = p[h] - mu; var += d * d; }
    var *= (1.f / HH);
    const float rstd = rsqrtf(var + 1e-5f);
#pragma unroll
    for (int h = 0; h < HH; ++h)
        p[h] = (p[h] - mu) * rstd * sScale[h] + sOff[h];

    // ---- matmul1: hidden[k] = sum_h p[h] * Wh[h][k]  (packed f32x2) ----
    unsigned long long acc[16];
#pragma unroll
    for (int q = 0; q < 16; ++q) acc[q] = 0ull;
#pragma unroll
    for (int h = 0; h < HH; ++h) {
        unsigned long long ph = pk2(p[h], p[h]);
        const ulonglong2* w = reinterpret_cast<const ulonglong2*>(&sWh[h * HH]);
#pragma unroll
        for (int q = 0; q < 8; ++q) {
            ulonglong2 ww = w[q];
            fma2(acc[2 * q],     ph, ww.x);
            fma2(acc[2 * q + 1], ph, ww.y);
        }
    }

    float hv[HH];
#pragma unroll
    for (int q = 0; q < 16; ++q) {
        float2 v = up2(acc[q]);
        hv[2 * q]     = gelu_tanh(v.x);
        hv[2 * q + 1] = gelu_tanh(v.y);
    }

    // ---- matmul2: out[s] = sum_k hv[k] * Wo[k][s], 2 chunks of 32 outputs ----
#pragma unroll
    for (int sc = 0; sc < 2; ++sc) {
        unsigned long long a2[16];
#pragma unroll
        for (int q = 0; q < 16; ++q) a2[q] = 0ull;
#pragma unroll
        for (int k = 0; k < HH; ++k) {
            unsigned long long hk = pk2(hv[k], hv[k]);
            const ulonglong2* w =
                reinterpret_cast<const ulonglong2*>(&sWo[k * OUTS + sc * 32]);
#pragma unroll
            for (int q = 0; q < 8; ++q) {
                ulonglong2 ww = w[q];
                fma2(a2[2 * q],     hk, ww.x);
                fma2(a2[2 * q + 1], hk, ww.y);
            }
        }
#pragma unroll
        for (int q = 0; q < 8; ++q) {
            float2 v0 = up2(a2[2 * q]);
            float2 v1 = up2(a2[2 * q + 1]);
            __stcs(&out4[sc * 8 + q], make_float4(v0.x, v0.y, v1.x, v1.y));
        }
    }
}

// ---------------------------------------------------------------------------
extern "C" void kernel_launch(void* const* d_in, const int* in_sizes, int n_in,
                              void* d_out, int out_size) {
    const float* local = (const float*)d_in[0];
    const int*   resi  = (const int*)d_in[1];
    const int*   chain = (const int*)d_in[2];
    const int*   batch = (const int*)d_in[3];
    const int*   mask  = (const int*)d_in[4];    // bool materialized as 4-byte elems
    const float* Wl    = (const float*)d_in[5];
    const float* Wr    = (const float*)d_in[6];
    const float* Wrel  = (const float*)d_in[7];
    const float* lns   = (const float*)d_in[8];
    const float* lno   = (const float*)d_in[9];
    const float* Wh    = (const float*)d_in[10];
    const float* Wo    = (const float*)d_in[11];
    float*       out   = (float*)d_out;

    proj_kernel<<<256, 256>>>(local, Wl, Wr);

    dim3 grid(NN / 16, NN / 16);
    pair_kernel<<<grid, 256>>>(resi, chain, batch, mask, Wrel, lns, lno, Wh, Wo, out);
}

// round 3
// speedup vs baseline: 1.3014x; 1.3014x over previous
#include <cuda_runtime.h>
#include <cstdint>

#define NN 1024
#define DD 256
#define HH 32
#define OUTS 64
#define NBINS 65
#define SPITCH 260   // pair-tile smem pitch (rows=256 + pad, mult of 4 for float4)

// scratch for projections (device globals: no allocation allowed)
__device__ float g_left[NN * HH];
__device__ float g_right[NN * HH];

// ---------------------------------------------------------------------------
// packed f32x2 helpers
// ---------------------------------------------------------------------------
__device__ __forceinline__ unsigned long long pk2(float a, float b) {
    unsigned long long r;
    asm("mov.b64 %0, {%1, %2};" : "=l"(r) : "f"(a), "f"(b));
    return r;
}
__device__ __forceinline__ void fma2(unsigned long long& d,
                                     unsigned long long a,
                                     unsigned long long b) {
    asm("fma.rn.f32x2 %0, %1, %2, %0;" : "+l"(d) : "l"(a), "l"(b));
}
__device__ __forceinline__ float2 up2(unsigned long long a) {
    float2 f;
    asm("mov.b64 {%0, %1}, %2;" : "=f"(f.x), "=f"(f.y) : "l"(a));
    return f;
}

// JAX approximate (tanh) GELU; tanh(u) = 1 - 2/(1+exp(2u))
__device__ __forceinline__ float gelu_tanh(float x) {
    float u = 0.7978845608028654f * (x + 0.044715f * x * x * x);
    float e = __expf(2.0f * u);
    float t = 1.0f - __fdividef(2.0f, 1.0f + e);
    return 0.5f * x * (1.0f + t);
}

// ---------------------------------------------------------------------------
// Projection: left = local @ W_left, right = local @ W_right   [1024,256]@[256,32]
// ---------------------------------------------------------------------------
__global__ void proj_kernel(const float* __restrict__ local,
                            const float* __restrict__ Wl,
                            const float* __restrict__ Wr) {
    int idx  = blockIdx.x * blockDim.x + threadIdx.x;
    int h    = idx & 31;
    int n    = (idx >> 5) & (NN - 1);
    int side = idx >> 15;
    const float* W = side ? Wr : Wl;
    float*       g = side ? g_right : g_left;

    const float4* row4 = reinterpret_cast<const float4*>(local + (size_t)n * DD);
    float acc = 0.f;
#pragma unroll
    for (int d4 = 0; d4 < DD / 4; ++d4) {
        float4 r = row4[d4];
        int d = d4 * 4;
        acc += r.x * W[(d + 0) * HH + h];
        acc += r.y * W[(d + 1) * HH + h];
        acc += r.z * W[(d + 2) * HH + h];
        acc += r.w * W[(d + 3) * HH + h];
    }
    g[n * HH + h] = acc;
}

// ---------------------------------------------------------------------------
// Shared memory layout (floats) — dynamic
// ---------------------------------------------------------------------------
#define OFF_WH   0                      // 32*32   = 1024
#define OFF_WO   (OFF_WH + 1024)        // 32*64   = 2048
#define OFF_REL  (OFF_WO + 2048)        // 65*33   = 2145
#define OFF_L    (OFF_REL + 2148)       // 16*33   = 528
#define OFF_R    (OFF_L + 528)          // 528
#define OFF_SC   (OFF_R + 528)          // 32
#define OFF_OF   (OFF_SC + 32)          // 32
#define OFF_PM   (OFF_OF + 32)          // 256 (as int)
#define OFF_P    (OFF_PM + 256)         // 32*SPITCH = 8320
#define OFF_HID  (OFF_P + 32*SPITCH)    // 8320
#define SMEM_FLOATS (OFF_HID + 32*SPITCH)
#define SMEM_BYTES  (SMEM_FLOATS * 4)

// ---------------------------------------------------------------------------
// Main fused pair kernel: 16x16 pairs per block; two register-blocked GEMMs
// ---------------------------------------------------------------------------
__global__ __launch_bounds__(256, 2)
void pair_kernel(const int* __restrict__ resi,
                 const int* __restrict__ chain,
                 const int* __restrict__ batch,
                 const int* __restrict__ mask,
                 const float* __restrict__ W_relpos,
                 const float* __restrict__ ln_scale,
                 const float* __restrict__ ln_offset,
                 const float* __restrict__ W_hidden,
                 const float* __restrict__ W_out,
                 float* __restrict__ out) {
    extern __shared__ float sm[];
    float* sWh  = sm + OFF_WH;
    float* sWo  = sm + OFF_WO;
    float* sRel = sm + OFF_REL;
    float* sL   = sm + OFF_L;
    float* sR   = sm + OFF_R;
    float* sSc  = sm + OFF_SC;
    float* sOf  = sm + OFF_OF;
    int*   sPM  = (int*)(sm + OFF_PM);
    float* sP   = sm + OFF_P;
    float* sHid = sm + OFF_HID;

    const int t  = threadIdx.x;
    const int i0 = blockIdx.y * 16, j0 = blockIdx.x * 16;
    const int ty = t >> 4, tx = t & 15;
    const int i  = i0 + ty, j = j0 + tx;
    const int rg = t >> 3, cg = t & 7;   // GEMM thread tiling: 32 rowgroups x 8 colgroups

    // ---- mask, block-level early exit ----
    const int  bi = batch[i], bj = batch[j];
    const bool same_batch = (bi == bj);
    const bool pm = same_batch && (mask[i] != 0) && (mask[j] != 0);
    sPM[t] = pm;
    const int any = __syncthreads_or((int)pm);
    if (!any) {
        const float4 z = make_float4(0.f, 0.f, 0.f, 0.f);
#pragma unroll
        for (int r8 = 0; r8 < 8; ++r8) {
            int r  = rg * 8 + r8;
            int ii = i0 + (r >> 4), jj = j0 + (r & 15);
            float4* o4 = reinterpret_cast<float4*>(
                out + ((size_t)(ii * NN + jj)) * OUTS + cg * 8);
            __stcs(o4, z);
            __stcs(o4 + 1, z);
        }
        return;
    }

    // ---- stage weights / tiles ----
    for (int k = t; k < HH * HH; k += 256) sWh[k] = W_hidden[k];
    for (int k = t; k < HH * OUTS; k += 256) sWo[k] = W_out[k];
    for (int k = t; k < NBINS * HH; k += 256)
        sRel[(k >> 5) * 33 + (k & 31)] = W_relpos[k];
    for (int k = t; k < 16 * HH; k += 256) {
        int r = k >> 5, h = k & 31;
        sL[r * 33 + h] = g_left[(i0 + r) * HH + h];
        sR[r * 33 + h] = g_right[(j0 + r) * HH + h];
    }
    if (t < HH) { sSc[t] = ln_scale[t]; sOf[t] = ln_offset[t]; }
    __syncthreads();

    // ---- Phase A: pair build + layernorm, write K-major to sP[k][row] ----
    {
        const bool same_chain = same_batch && (chain[i] == chain[j]);
        int diff = resi[i] - resi[j];
        diff = min(max(diff, -32), 32) + 32;

        const float* relrow = &sRel[diff * 33];
        const float* lrow   = &sL[ty * 33];
        const float* rrow   = &sR[tx * 33];

        float p[HH];
        float mu = 0.f;
#pragma unroll
        for (int h = 0; h < HH; ++h) {
            float v = lrow[h] + rrow[h];
            if (same_chain) v += relrow[h];
            p[h] = v;
            mu += v;
        }
        mu *= (1.f / HH);
        float var = 0.f;
#pragma unroll
        for (int h = 0; h < HH; ++h) { float d = p[h] - mu; var += d * d; }
        var *= (1.f / HH);
        const float rstd = rsqrtf(var + 1e-5f);
#pragma unroll
        for (int h = 0; h < HH; ++h)
            sP[h * SPITCH + t] = (p[h] - mu) * rstd * sSc[h] + sOf[h];
    }
    __syncthreads();

    // ---- GEMM1: hid[256x32] = gelu(sP^T @ Wh); 8 rows x 4 cols per thread ----
    {
        unsigned long long acc[4][4];   // [rowpair][col] ; rowpair packs rows 2rp,2rp+1
#pragma unroll
        for (int a = 0; a < 4; ++a)
#pragma unroll
            for (int b = 0; b < 4; ++b) acc[a][b] = 0ull;

#pragma unroll
        for (int k = 0; k < HH; ++k) {
            const float4 a0 = *reinterpret_cast<const float4*>(&sP[k * SPITCH + rg * 8]);
            const float4 a1 = *reinterpret_cast<const float4*>(&sP[k * SPITCH + rg * 8 + 4]);
            const float4 b  = *reinterpret_cast<const float4*>(&sWh[k * HH + cg * 4]);
            unsigned long long ap[4] = {pk2(a0.x, a0.y), pk2(a0.z, a0.w),
                                        pk2(a1.x, a1.y), pk2(a1.z, a1.w)};
            unsigned long long bd[4] = {pk2(b.x, b.x), pk2(b.y, b.y),
                                        pk2(b.z, b.z), pk2(b.w, b.w)};
#pragma unroll
            for (int rp = 0; rp < 4; ++rp)
#pragma unroll
                for (int c = 0; c < 4; ++c) fma2(acc[rp][c], ap[rp], bd[c]);
        }

        float g[8][4];
#pragma unroll
        for (int rp = 0; rp < 4; ++rp)
#pragma unroll
            for (int c = 0; c < 4; ++c) {
                float2 v = up2(acc[rp][c]);
                g[2 * rp][c]     = gelu_tanh(v.x);
                g[2 * rp + 1][c] = gelu_tanh(v.y);
            }
#pragma unroll
        for (int c = 0; c < 4; ++c) {
            const int cc = cg * 4 + c;
            *reinterpret_cast<float4*>(&sHid[cc * SPITCH + rg * 8]) =
                make_float4(g[0][c], g[1][c], g[2][c], g[3][c]);
            *reinterpret_cast<float4*>(&sHid[cc * SPITCH + rg * 8 + 4]) =
                make_float4(g[4][c], g[5][c], g[6][c], g[7][c]);
        }
    }
    __syncthreads();

    // ---- GEMM2: out[256x64] = hid @ Wo; 8 rows x 8 cols per thread ----
    {
        unsigned long long acc[8][4];   // [row][colpair] ; colpair packs cols 2cp,2cp+1
#pragma unroll
        for (int a = 0; a < 8; ++a)
#pragma unroll
            for (int b = 0; b < 4; ++b) acc[a][b] = 0ull;

#pragma unroll
        for (int k = 0; k < HH; ++k) {
            const float4 a0 = *reinterpret_cast<const float4*>(&sHid[k * SPITCH + rg * 8]);
            const float4 a1 = *reinterpret_cast<const float4*>(&sHid[k * SPITCH + rg * 8 + 4]);
            const float4 b0 = *reinterpret_cast<const float4*>(&sWo[k * OUTS + cg * 8]);
            const float4 b1 = *reinterpret_cast<const float4*>(&sWo[k * OUTS + cg * 8 + 4]);
            unsigned long long bp[4] = {pk2(b0.x, b0.y), pk2(b0.z, b0.w),
                                        pk2(b1.x, b1.y), pk2(b1.z, b1.w)};
            const float av[8] = {a0.x, a0.y, a0.z, a0.w, a1.x, a1.y, a1.z, a1.w};
#pragma unroll
            for (int r8 = 0; r8 < 8; ++r8) {
                unsigned long long ad = pk2(av[r8], av[r8]);
#pragma unroll
                for (int cp = 0; cp < 4; ++cp) fma2(acc[r8][cp], ad, bp[cp]);
            }
        }

        const float4 z = make_float4(0.f, 0.f, 0.f, 0.f);
#pragma unroll
        for (int r8 = 0; r8 < 8; ++r8) {
            const int r  = rg * 8 + r8;
            const int ii = i0 + (r >> 4), jj = j0 + (r & 15);
            float4* o4 = reinterpret_cast<float4*>(
                out + ((size_t)(ii * NN + jj)) * OUTS + cg * 8);
            if (sPM[r]) {
                float2 v0 = up2(acc[r8][0]), v1 = up2(acc[r8][1]);
                float2 v2 = up2(acc[r8][2]), v3 = up2(acc[r8][3]);
                __stcs(o4,     make_float4(v0.x, v0.y, v1.x, v1.y));
                __stcs(o4 + 1, make_float4(v2.x, v2.y, v3.x, v3.y));
            } else {
                __stcs(o4, z);
                __stcs(o4 + 1, z);
            }
        }
    }
}

// ---------------------------------------------------------------------------
extern "C" void kernel_launch(void* const* d_in, const int* in_sizes, int n_in,
                              void* d_out, int out_size) {
    const float* local = (const float*)d_in[0];
    const int*   resi  = (const int*)d_in[1];
    const int*   chain = (const int*)d_in[2];
    const int*   batch = (const int*)d_in[3];
    const int*   mask  = (const int*)d_in[4];
    const float* Wl    = (const float*)d_in[5];
    const float* Wr    = (const float*)d_in[6];
    const float* Wrel  = (const float*)d_in[7];
    const float* lns   = (const float*)d_in[8];
    const float* lno   = (const float*)d_in[9];
    const float* Wh    = (const float*)d_in[10];
    const float* Wo    = (const float*)d_in[11];
    float*       out   = (float*)d_out;

    static bool attr_set = false;
    if (!attr_set) {
        cudaFuncSetAttribute(pair_kernel,
                             cudaFuncAttributeMaxDynamicSharedMemorySize,
                             SMEM_BYTES);
        attr_set = true;
    }

    proj_kernel<<<256, 256>>>(local, Wl, Wr);

    dim3 grid(NN / 16, NN / 16);
    pair_kernel<<<grid, 256, SMEM_BYTES>>>(resi, chain, batch, mask, Wrel,
                                           lns, lno, Wh, Wo, out);
}